// round 15
// baseline (speedup 1.0000x reference)
#include <cuda_runtime.h>
#include <cuda_bf16.h>
#include <cuda_fp16.h>
#include <cstdint>

#define N_NODES 65536
#define N_EDGES 1048576
#define HDIM    128
#define IN_F    5
#define N_GRAPH 16
#define ELEC    32
#define BSZ     128
#define LCONV   63   // (128-3)/2+1

// ---------------- device scratch (no allocations allowed) ----------------
__device__ float           g_h   [N_NODES * HDIM];   // 32 MB fp32 h
__device__ __nv_bfloat16   g_hb  [N_NODES * HDIM];   // 16 MB bf16 mirror of h
__device__ __nv_bfloat16   g_aggb[N_NODES * HDIM];   // 16 MB bf16 agg (layer 2)
__device__ __nv_bfloat16   g_aggc[N_NODES * 16];     // 2 MB compact agg (layer 1)
__device__ __nv_bfloat16   g_qtb [2 * 384 * HDIM];   // bf16 Qt = W_ih @ Wg^T
__device__ __nv_bfloat16   g_whb [384 * HDIM];       // bf16 w_hh
__device__ float           g_v   [BSZ * ELEC * LCONV]; // 1 MB conv output
// CSR scratch
__device__ int   g_deg [N_NODES];
__device__ int   g_bsum[256];
__device__ int   g_off [N_NODES + 1];
__device__ int   g_cur [N_NODES];
__device__ int   g_csrc[N_EDGES];
__device__ float g_cw  [N_EDGES];

// ---------------- helpers ----------------
__device__ __forceinline__ unsigned int f2tf(float f) {
    unsigned int u; asm("cvt.rna.tf32.f32 %0, %1;" : "=r"(u) : "f"(f)); return u;
}

__device__ __forceinline__ void mma_tf32(float* c, const unsigned int* a, const unsigned int* b) {
    asm("mma.sync.aligned.m16n8k8.row.col.f32.tf32.tf32.f32 "
        "{%0,%1,%2,%3},{%4,%5,%6,%7},{%8,%9},{%0,%1,%2,%3};"
        : "+f"(c[0]), "+f"(c[1]), "+f"(c[2]), "+f"(c[3])
        : "r"(a[0]), "r"(a[1]), "r"(a[2]), "r"(a[3]), "r"(b[0]), "r"(b[1]));
}

__device__ __forceinline__ void mma_bf16(float* c, const unsigned int* a, const unsigned int* b) {
    asm("mma.sync.aligned.m16n8k16.row.col.f32.bf16.bf16.f32 "
        "{%0,%1,%2,%3},{%4,%5,%6,%7},{%8,%9},{%0,%1,%2,%3};"
        : "+f"(c[0]), "+f"(c[1]), "+f"(c[2]), "+f"(c[3])
        : "r"(a[0]), "r"(a[1]), "r"(a[2]), "r"(a[3]), "r"(b[0]), "r"(b[1]));
}

__device__ __forceinline__ void ldsm4(unsigned* r, unsigned addr) {
    asm volatile("ldmatrix.sync.aligned.m8n8.x4.shared.b16 {%0,%1,%2,%3}, [%4];"
        : "=r"(r[0]), "=r"(r[1]), "=r"(r[2]), "=r"(r[3]) : "r"(addr));
}

__device__ __forceinline__ void cp16(unsigned saddr, const void* gptr) {
    asm volatile("cp.async.cg.shared.global [%0], [%1], 16;" :: "r"(saddr), "l"(gptr));
}

__global__ void zero_kernel(float4* p, int n4) {
    int i = blockIdx.x * blockDim.x + threadIdx.x;
    if (i < n4) p[i] = make_float4(0.f, 0.f, 0.f, 0.f);
}

// ---------------- CSR build (parallel hierarchical scan) ----------------
__global__ void count_kernel(const int* __restrict__ ei, int* __restrict__ deg) {
    int e = blockIdx.x * blockDim.x + threadIdx.x;
    if (e < N_EDGES) atomicAdd(&deg[ei[N_EDGES + e]], 1);
}

__global__ void bsum_kernel(const int* __restrict__ deg, int* __restrict__ bsum) {
    __shared__ int s[256];
    int t = threadIdx.x;
    s[t] = deg[blockIdx.x * 256 + t];
    __syncthreads();
    #pragma unroll
    for (int o = 128; o; o >>= 1) {
        if (t < o) s[t] += s[t + o];
        __syncthreads();
    }
    if (t == 0) bsum[blockIdx.x] = s[0];
}

__global__ void scan_tops_kernel(int* __restrict__ bsum) {
    __shared__ int s[256];
    int t = threadIdx.x;
    int own = bsum[t];
    s[t] = own;
    __syncthreads();
    for (int o = 1; o < 256; o <<= 1) {
        int v = (t >= o) ? s[t - o] : 0;
        __syncthreads();
        s[t] += v;
        __syncthreads();
    }
    bsum[t] = s[t] - own;
}

__global__ void off_kernel(const int* __restrict__ deg, const int* __restrict__ bpre,
                           int* __restrict__ off, int* __restrict__ cur) {
    __shared__ int s[256];
    int t = threadIdx.x;
    int g = blockIdx.x * 256 + t;
    int own = deg[g];
    s[t] = own;
    __syncthreads();
    for (int o = 1; o < 256; o <<= 1) {
        int v = (t >= o) ? s[t - o] : 0;
        __syncthreads();
        s[t] += v;
        __syncthreads();
    }
    int val = bpre[blockIdx.x] + s[t] - own;
    off[g] = val;
    cur[g] = val;
    if (g == N_NODES - 1) off[N_NODES] = bpre[blockIdx.x] + s[t];
}

__global__ void fill_kernel(const int* __restrict__ ei, const float* __restrict__ ea,
                            int* __restrict__ cur, int* __restrict__ csrc,
                            float* __restrict__ cw,
                            const float* __restrict__ whh, __nv_bfloat16* __restrict__ whb) {
    int e = blockIdx.x * blockDim.x + threadIdx.x;
    if (e >= N_EDGES) return;
    if (e < 384 * HDIM) whb[e] = __float2bfloat16_rn(whh[e]);
    int d = ei[N_EDGES + e];
    int pos = atomicAdd(&cur[d], 1);
    csrc[pos] = ei[e];
    cw[pos]   = ea[e];
}

// ---------------- layer-2 gather: bf16 in/out, fp32 accumulate, 4-edge unroll ----------------
__global__ void aggb_kernel(const int* __restrict__ off, const int* __restrict__ csrc,
                            const float* __restrict__ cw, const uint4* __restrict__ src,
                            uint4* __restrict__ dst) {
    int gid  = blockIdx.x * blockDim.x + threadIdx.x;
    int node = gid >> 4;
    int lane = gid & 15;
    if (node >= N_NODES) return;
    int e0 = __ldg(off + node), e1 = __ldg(off + node + 1);
    float acc[8] = {0.f, 0.f, 0.f, 0.f, 0.f, 0.f, 0.f, 0.f};
    int e = e0;
    for (; e + 3 < e1; e += 4) {
        int   s0 = __ldg(csrc + e),     s1 = __ldg(csrc + e + 1);
        int   s2 = __ldg(csrc + e + 2), s3 = __ldg(csrc + e + 3);
        float w0 = __ldg(cw + e),       w1 = __ldg(cw + e + 1);
        float w2 = __ldg(cw + e + 2),   w3 = __ldg(cw + e + 3);
        uint4 v0 = __ldg(src + (size_t)s0 * 16 + lane);
        uint4 v1 = __ldg(src + (size_t)s1 * 16 + lane);
        uint4 v2 = __ldg(src + (size_t)s2 * 16 + lane);
        uint4 v3 = __ldg(src + (size_t)s3 * 16 + lane);
        const unsigned* p0 = &v0.x; const unsigned* p1 = &v1.x;
        const unsigned* p2 = &v2.x; const unsigned* p3 = &v3.x;
        #pragma unroll
        for (int q = 0; q < 4; q++) {
            float2 f0 = __bfloat1622float2(*reinterpret_cast<const __nv_bfloat162*>(&p0[q]));
            float2 f1 = __bfloat1622float2(*reinterpret_cast<const __nv_bfloat162*>(&p1[q]));
            float2 f2 = __bfloat1622float2(*reinterpret_cast<const __nv_bfloat162*>(&p2[q]));
            float2 f3 = __bfloat1622float2(*reinterpret_cast<const __nv_bfloat162*>(&p3[q]));
            acc[2*q]   += w0 * f0.x + w1 * f1.x + w2 * f2.x + w3 * f3.x;
            acc[2*q+1] += w0 * f0.y + w1 * f1.y + w2 * f2.y + w3 * f3.y;
        }
    }
    for (; e < e1; e++) {
        int   sA = __ldg(csrc + e);
        float wA = __ldg(cw + e);
        uint4 vA = __ldg(src + (size_t)sA * 16 + lane);
        const unsigned* pa = &vA.x;
        #pragma unroll
        for (int q = 0; q < 4; q++) {
            float2 fa = __bfloat1622float2(*reinterpret_cast<const __nv_bfloat162*>(&pa[q]));
            acc[2*q]   += wA * fa.x;
            acc[2*q+1] += wA * fa.y;
        }
    }
    uint4 o;
    unsigned* po = &o.x;
    #pragma unroll
    for (int q = 0; q < 4; q++) {
        __nv_bfloat162 p = __floats2bfloat162_rn(acc[2*q], acc[2*q+1]);
        po[q] = *reinterpret_cast<unsigned*>(&p);
    }
    dst[(size_t)node * 16 + lane] = o;
}

// ---------------- layer-1 gather: from x, 8 lanes/node -> compact bf16 agg [N][16] ----------------
__global__ void agg1c_kernel(const int* __restrict__ off, const int* __restrict__ csrc,
                             const float* __restrict__ cw, const float* __restrict__ x,
                             uint2* __restrict__ dst) {
    int gid  = blockIdx.x * blockDim.x + threadIdx.x;
    int node = gid >> 3;
    int lane = gid & 7;
    if (node >= N_NODES) return;
    int e0 = __ldg(off + node), e1 = __ldg(off + node + 1);
    float a0 = 0.f, a1 = 0.f, a2 = 0.f, a3 = 0.f, a4 = 0.f;
    for (int e = e0 + lane; e < e1; e += 8) {
        int   s = __ldg(csrc + e);
        float w = __ldg(cw + e);
        const float* xs = x + (size_t)s * IN_F;
        a0 += w * __ldg(xs);
        a1 += w * __ldg(xs + 1);
        a2 += w * __ldg(xs + 2);
        a3 += w * __ldg(xs + 3);
        a4 += w * __ldg(xs + 4);
    }
    #pragma unroll
    for (int o = 4; o; o >>= 1) {
        a0 += __shfl_xor_sync(0xffffffffu, a0, o);
        a1 += __shfl_xor_sync(0xffffffffu, a1, o);
        a2 += __shfl_xor_sync(0xffffffffu, a2, o);
        a3 += __shfl_xor_sync(0xffffffffu, a3, o);
        a4 += __shfl_xor_sync(0xffffffffu, a4, o);
    }
    if (lane < 4) {
        uint2 o = make_uint2(0u, 0u);
        if (lane == 0) {
            __nv_bfloat162 p0 = __floats2bfloat162_rn(a0, a1);
            __nv_bfloat162 p1 = __floats2bfloat162_rn(a2, a3);
            o.x = *reinterpret_cast<unsigned*>(&p0);
            o.y = *reinterpret_cast<unsigned*>(&p1);
        } else if (lane == 1) {
            __nv_bfloat162 p0 = __floats2bfloat162_rn(a4, 0.f);
            o.x = *reinterpret_cast<unsigned*>(&p0);
        }
        dst[(size_t)node * 4 + lane] = o;
    }
}

// ---------------- Qt precompute: qtb[l] = bf16(W_ih @ Wg_l^T), [384][128] ----------------
#define AS_STR 132
#define BS_STR 136
#define GEMM_SMEM ((128 * AS_STR + 128 * BS_STR) * 4)

__global__ void gemm_qt(const float* __restrict__ w_ih, const float* __restrict__ gconv_w,
                        __nv_bfloat16* __restrict__ qtb) {
    extern __shared__ unsigned int sm[];
    unsigned int* As = sm;
    unsigned int* Bs = sm + 128 * AS_STR;

    const float* A = w_ih;
    const float* Bsrc = gconv_w + (size_t)blockIdx.z * 16384;
    __nv_bfloat16* C = qtb + (size_t)blockIdx.z * 49152;

    int t  = threadIdx.x;
    int rb = blockIdx.x * 128;

    {
        const float4* A4 = reinterpret_cast<const float4*>(A) + (size_t)rb * 32;
        #pragma unroll
        for (int i = t; i < 128 * 32; i += 256) {
            int r = i >> 5, k4 = i & 31;
            float4 v = A4[r * 32 + k4];
            uint4 u = make_uint4(f2tf(v.x), f2tf(v.y), f2tf(v.z), f2tf(v.w));
            *reinterpret_cast<uint4*>(&As[r * AS_STR + k4 * 4]) = u;
        }
    }
    {
        const float4* B4 = reinterpret_cast<const float4*>(Bsrc);
        #pragma unroll
        for (int i = t; i < 128 * 32; i += 256) {
            int n = i >> 5, k4 = i & 31;
            float4 v = B4[n * 32 + k4];
            uint4 u = make_uint4(f2tf(v.x), f2tf(v.y), f2tf(v.z), f2tf(v.w));
            *reinterpret_cast<uint4*>(&Bs[n * BS_STR + k4 * 4]) = u;
        }
    }
    __syncthreads();

    int warp = t >> 5, lane = t & 31;
    int wm = (warp >> 2) * 64;
    int wn = (warp & 3) * 32;
    int lr = lane >> 2, lc = lane & 3;

    float acc[4][4][4];
    #pragma unroll
    for (int mt = 0; mt < 4; mt++)
        #pragma unroll
        for (int nt = 0; nt < 4; nt++)
            #pragma unroll
            for (int q = 0; q < 4; q++) acc[mt][nt][q] = 0.f;

    #pragma unroll
    for (int kk = 0; kk < 16; kk++) {
        int k0 = kk * 8 + lc;
        unsigned int a[4][4], b[4][2];
        #pragma unroll
        for (int mt = 0; mt < 4; mt++) {
            int r = wm + mt * 16 + lr;
            a[mt][0] = As[r * AS_STR + k0];
            a[mt][1] = As[(r + 8) * AS_STR + k0];
            a[mt][2] = As[r * AS_STR + k0 + 4];
            a[mt][3] = As[(r + 8) * AS_STR + k0 + 4];
        }
        #pragma unroll
        for (int nt = 0; nt < 4; nt++) {
            int n = wn + nt * 8 + lr;
            b[nt][0] = Bs[n * BS_STR + k0];
            b[nt][1] = Bs[n * BS_STR + k0 + 4];
        }
        #pragma unroll
        for (int mt = 0; mt < 4; mt++)
            #pragma unroll
            for (int nt = 0; nt < 4; nt++)
                mma_tf32(acc[mt][nt], a[mt], b[nt]);
    }

    #pragma unroll
    for (int nt = 0; nt < 4; nt++) {
        int c = wn + nt * 8 + lc * 2;
        #pragma unroll
        for (int mt = 0; mt < 4; mt++) {
            int r = rb + wm + mt * 16 + lr;
            __nv_bfloat162 p0 = __floats2bfloat162_rn(acc[mt][nt][0], acc[mt][nt][1]);
            __nv_bfloat162 p1 = __floats2bfloat162_rn(acc[mt][nt][2], acc[mt][nt][3]);
            *reinterpret_cast<unsigned*>(&C[(size_t)r * 128 + c]) =
                *reinterpret_cast<unsigned*>(&p0);
            *reinterpret_cast<unsigned*>(&C[(size_t)(r + 8) * 128 + c]) =
                *reinterpret_cast<unsigned*>(&p1);
        }
    }
}

// ---------------- shared GRU epilogue ----------------
template <int LAYER1>
__device__ __forceinline__ void gru_epilogue(
    float acc[2][3][2][4], __half2 gi_st[2][3][2][2],
    float* h, __nv_bfloat16* hb, const float* xx, const float* b_ih, const float* b_hh,
    int rb, int wr, int wc, int lr, int lc) {
    #pragma unroll
    for (int nt = 0; nt < 2; nt++) {
        int c = wc * 16 + nt * 8 + lc * 2;
        float bir0 = __ldg(b_ih + c),       bir1 = __ldg(b_ih + c + 1);
        float biz0 = __ldg(b_ih + 128 + c), biz1 = __ldg(b_ih + 128 + c + 1);
        float bin0 = __ldg(b_ih + 256 + c), bin1 = __ldg(b_ih + 256 + c + 1);
        float bhr0 = __ldg(b_hh + c),       bhr1 = __ldg(b_hh + c + 1);
        float bhz0 = __ldg(b_hh + 128 + c), bhz1 = __ldg(b_hh + 128 + c + 1);
        float bhn0 = __ldg(b_hh + 256 + c), bhn1 = __ldg(b_hh + 256 + c + 1);
        #pragma unroll
        for (int mt = 0; mt < 2; mt++) {
            #pragma unroll
            for (int half = 0; half < 2; half++) {
                int row = wr * 32 + mt * 16 + lr + half * 8;
                int q0 = half * 2;
                float2 gir = __half22float2(gi_st[mt][0][nt][half]);
                float2 giz = __half22float2(gi_st[mt][1][nt][half]);
                float2 gin = __half22float2(gi_st[mt][2][nt][half]);
                float ghr0 = acc[mt][0][nt][q0], ghr1 = acc[mt][0][nt][q0 + 1];
                float ghz0 = acc[mt][1][nt][q0], ghz1 = acc[mt][1][nt][q0 + 1];
                float ghn0 = acc[mt][2][nt][q0], ghn1 = acc[mt][2][nt][q0 + 1];
                float2 hold;
                if (LAYER1) {
                    hold = make_float2(0.f, 0.f);
                    if (c < 5) {
                        hold.x = __ldg(xx + (size_t)(rb + row) * IN_F + c);
                        if (c + 1 < 5)
                            hold.y = __ldg(xx + (size_t)(rb + row) * IN_F + c + 1);
                    }
                } else {
                    hold = *reinterpret_cast<float2*>(&h[(size_t)(rb + row) * 128 + c]);
                }
                float r0 = 1.f / (1.f + __expf(-(gir.x + ghr0 + bir0 + bhr0)));
                float z0 = 1.f / (1.f + __expf(-(giz.x + ghz0 + biz0 + bhz0)));
                float n0 = tanhf(gin.x + bin0 + r0 * (ghn0 + bhn0));
                float r1 = 1.f / (1.f + __expf(-(gir.y + ghr1 + bir1 + bhr1)));
                float z1 = 1.f / (1.f + __expf(-(giz.y + ghz1 + biz1 + bhz1)));
                float n1 = tanhf(gin.y + bin1 + r1 * (ghn1 + bhn1));
                float hx = (1.f - z0) * n0 + z0 * hold.x;
                float hy = (1.f - z1) * n1 + z1 * hold.y;
                *reinterpret_cast<float2*>(&h[(size_t)(rb + row) * 128 + c]) = make_float2(hx, hy);
                if (LAYER1) {
                    __nv_bfloat162 hp = __floats2bfloat162_rn(hx, hy);
                    *reinterpret_cast<unsigned*>(&hb[(size_t)(rb + row) * 128 + c]) =
                        *reinterpret_cast<unsigned*>(&hp);
                }
            }
        }
    }
}

// ---------------- layer-1 fused GRU: exact K=16 GEMMs; inputs from x ----------------
#define R1_STR 12
#define O_B0 (64 * R1_STR)
#define O_A1 (O_B0 + 384 * R1_STR)
#define O_B1 (O_A1 + 64 * R1_STR)
#define GRU1_SMEM ((O_B1 + 384 * R1_STR) * 4)

__global__ void __launch_bounds__(512, 1)
gru1_fused(const __nv_bfloat16* __restrict__ aggc, float* __restrict__ h,
           __nv_bfloat16* __restrict__ hb, const float* __restrict__ x,
           const __nv_bfloat16* __restrict__ w0b, const __nv_bfloat16* __restrict__ whb,
           const float* __restrict__ b_ih, const float* __restrict__ b_hh) {
    extern __shared__ char smem[];
    unsigned sb = (unsigned)__cvta_generic_to_shared(smem);

    int t = threadIdx.x;
    int rb = blockIdx.x * 64;
    int warp = t >> 5, lane = t & 31;
    int wr = warp & 1;
    int wc = warp >> 1;
    int lr = lane >> 2, lc = lane & 3;

    {
        if (t < 128) {
            int r = t >> 1, wq = (t & 1) * 4;
            cp16(sb + (unsigned)(r * R1_STR + wq) * 4, aggc + (size_t)(rb + r) * 16 + (t & 1) * 8);
        }
        #pragma unroll
        for (int i = 0; i < 3; i++) {
            int idx = t + i * 512;
            const __nv_bfloat16* W = (idx < 768) ? w0b : whb;
            int base = (idx < 768) ? O_B0 : O_B1;
            int j = (idx < 768) ? idx : idx - 768;
            int n = j >> 1, wq = (j & 1) * 4;
            cp16(sb + (unsigned)(base + n * R1_STR + wq) * 4,
                 W + (size_t)n * 128 + (j & 1) * 8);
        }
        asm volatile("cp.async.commit_group;");
        if (t >= 256 && t < 320) {
            int r = t - 256;
            const float* xs = x + (size_t)(rb + r) * IN_F;
            float x0 = __ldg(xs), x1 = __ldg(xs + 1), x2 = __ldg(xs + 2);
            float x3 = __ldg(xs + 3), x4 = __ldg(xs + 4);
            __nv_bfloat162 p0 = __floats2bfloat162_rn(x0, x1);
            __nv_bfloat162 p1 = __floats2bfloat162_rn(x2, x3);
            __nv_bfloat162 p2 = __floats2bfloat162_rn(x4, 0.f);
            unsigned* dst = reinterpret_cast<unsigned*>(smem) + O_A1 + r * R1_STR;
            dst[0] = *reinterpret_cast<unsigned*>(&p0);
            dst[1] = *reinterpret_cast<unsigned*>(&p1);
            dst[2] = *reinterpret_cast<unsigned*>(&p2);
            #pragma unroll
            for (int q = 3; q < 12; q++) dst[q] = 0u;
        }
    }
    asm volatile("cp.async.wait_group 0;");
    __syncthreads();

    int lm_m = lane >> 3, lm_r = lane & 7;
    int aRow = wr * 32 + (lm_m & 1) * 8 + lm_r;
    int aWrd = (lm_m >> 1) * 4;
    int bRow = wc * 16 + (lm_m >> 1) * 8 + lm_r;
    int bWrd = (lm_m & 1) * 4;

    float acc[2][3][2][4];
    __half2 gi_st[2][3][2][2];

    #pragma unroll
    for (int phase = 0; phase < 2; phase++) {
        unsigned abase = sb + (unsigned)((phase ? O_A1 : 0)) * 4;
        unsigned bbase = sb + (unsigned)((phase ? O_B1 : O_B0)) * 4;
        unsigned a[2][4], b[3][4];
        #pragma unroll
        for (int mt = 0; mt < 2; mt++)
            ldsm4(a[mt], abase + (unsigned)((aRow + mt * 16) * R1_STR + aWrd) * 4);
        #pragma unroll
        for (int g = 0; g < 3; g++)
            ldsm4(b[g], bbase + (unsigned)((bRow + g * 128) * R1_STR + bWrd) * 4);
        #pragma unroll
        for (int mt = 0; mt < 2; mt++)
            #pragma unroll
            for (int g = 0; g < 3; g++)
                #pragma unroll
                for (int nt = 0; nt < 2; nt++)
                    #pragma unroll
                    for (int q = 0; q < 4; q++) acc[mt][g][nt][q] = 0.f;
        #pragma unroll
        for (int mt = 0; mt < 2; mt++)
            #pragma unroll
            for (int g = 0; g < 3; g++) {
                mma_bf16(acc[mt][g][0], a[mt], &b[g][0]);
                mma_bf16(acc[mt][g][1], a[mt], &b[g][2]);
            }
        if (phase == 0) {
            #pragma unroll
            for (int mt = 0; mt < 2; mt++)
                #pragma unroll
                for (int g = 0; g < 3; g++)
                    #pragma unroll
                    for (int nt = 0; nt < 2; nt++) {
                        gi_st[mt][g][nt][0] = __floats2half2_rn(acc[mt][g][nt][0], acc[mt][g][nt][1]);
                        gi_st[mt][g][nt][1] = __floats2half2_rn(acc[mt][g][nt][2], acc[mt][g][nt][3]);
                    }
        }
    }

    gru_epilogue<1>(acc, gi_st, h, hb, x, b_ih, b_hh, rb, wr, wc, lr, lc);
}

// ---------------- layer-2 fused GRU (bf16 MMA + ldmatrix, K=64 chunks) ----------------
#define RA_STR 36
#define RB_STR 36
#define OFF_BW (2 * 64 * RA_STR)
#define FUSED_SMEM ((OFF_BW + 2 * 384 * RB_STR) * 4)

__global__ void __launch_bounds__(512, 1)
gru_fused(const __nv_bfloat16* __restrict__ aggb, float* __restrict__ h,
          __nv_bfloat16* __restrict__ hb,
          const __nv_bfloat16* __restrict__ w0b, const __nv_bfloat16* __restrict__ whb,
          const float* __restrict__ b_ih, const float* __restrict__ b_hh) {
    extern __shared__ char smem[];
    unsigned sb = (unsigned)__cvta_generic_to_shared(smem);

    int t = threadIdx.x;
    int rb = blockIdx.x * 64;
    int warp = t >> 5, lane = t & 31;
    int wr = warp & 1;
    int wc = warp >> 1;
    int lr = lane >> 2, lc = lane & 3;

    const int nch0 = 2, total = 4;

    int la_r = t >> 3, la_w = t & 7;

    auto load_chunk = [&](int j, int buf) {
        const __nv_bfloat16* A; const __nv_bfloat16* W; int kcol;
        if (j < nch0) { A = aggb; W = w0b; kcol = j * 64; }
        else          { A = hb;   W = whb; kcol = (j - nch0) * 64; }
        cp16(sb + (unsigned)(buf * (64 * RA_STR) + la_r * RA_STR + la_w * 4) * 4,
             A + (size_t)(rb + la_r) * 128 + kcol + la_w * 8);
        #pragma unroll
        for (int i = 0; i < 6; i++) {
            int idx = t + i * 512;
            int n = idx >> 3, w = idx & 7;
            cp16(sb + (unsigned)(OFF_BW + buf * (384 * RB_STR) + n * RB_STR + w * 4) * 4,
                 W + (size_t)n * 128 + kcol + w * 8);
        }
        asm volatile("cp.async.commit_group;");
    };

    load_chunk(0, 0);
    load_chunk(1, 1);

    int lm_m = lane >> 3, lm_r = lane & 7;
    int aRow = wr * 32 + (lm_m & 1) * 8 + lm_r;
    int aWrd = (lm_m >> 1) * 4;
    int bRow = wc * 16 + (lm_m >> 1) * 8 + lm_r;
    int bWrd = (lm_m & 1) * 4;

    float acc[2][3][2][4];
    __half2 gi_st[2][3][2][2];

    for (int j = 0; j < total; j++) {
        int buf = j & 1;
        if (j == 0 || j == nch0) {
            #pragma unroll
            for (int mt = 0; mt < 2; mt++)
                #pragma unroll
                for (int g = 0; g < 3; g++)
                    #pragma unroll
                    for (int nt = 0; nt < 2; nt++)
                        #pragma unroll
                        for (int q = 0; q < 4; q++) acc[mt][g][nt][q] = 0.f;
        }
        if (j + 1 < total) asm volatile("cp.async.wait_group 1;");
        else               asm volatile("cp.async.wait_group 0;");
        __syncthreads();

        unsigned abase = sb + (unsigned)(buf * (64 * RA_STR)) * 4;
        unsigned bbase = sb + (unsigned)(OFF_BW + buf * (384 * RB_STR)) * 4;
        #pragma unroll
        for (int ks = 0; ks < 4; ks++) {
            unsigned a[2][4], b[3][4];
            #pragma unroll
            for (int mt = 0; mt < 2; mt++)
                ldsm4(a[mt], abase + (unsigned)((aRow + mt * 16) * RA_STR + aWrd + ks * 8) * 4);
            #pragma unroll
            for (int g = 0; g < 3; g++)
                ldsm4(b[g], bbase + (unsigned)((bRow + g * 128) * RB_STR + bWrd + ks * 8) * 4);
            #pragma unroll
            for (int mt = 0; mt < 2; mt++)
                #pragma unroll
                for (int g = 0; g < 3; g++) {
                    mma_bf16(acc[mt][g][0], a[mt], &b[g][0]);
                    mma_bf16(acc[mt][g][1], a[mt], &b[g][2]);
                }
        }
        __syncthreads();
        if (j + 2 < total) load_chunk(j + 2, buf);

        if (j == nch0 - 1) {
            #pragma unroll
            for (int mt = 0; mt < 2; mt++)
                #pragma unroll
                for (int g = 0; g < 3; g++)
                    #pragma unroll
                    for (int nt = 0; nt < 2; nt++) {
                        gi_st[mt][g][nt][0] = __floats2half2_rn(acc[mt][g][nt][0], acc[mt][g][nt][1]);
                        gi_st[mt][g][nt][1] = __floats2half2_rn(acc[mt][g][nt][2], acc[mt][g][nt][3]);
                    }
        }
    }

    gru_epilogue<0>(acc, gi_st, h, hb, nullptr, b_ih, b_hh, rb, wr, wc, lr, lc);
}

// ---------------- post: conv (wide) + lin (per-batch) ----------------
__global__ void conv_kernel(const float* __restrict__ h,
                            const float* __restrict__ conv_w, const float* __restrict__ conv_b,
                            float* __restrict__ v) {
    int b = blockIdx.x;
    int part = blockIdx.y;                 // 0..3, each covers 504 indices
    int t = threadIdx.x;
    __shared__ float cw[48];
    if (t < 48) cw[t] = conv_w[t];
    __syncthreads();
    float cb0 = conv_b[0];
    int base = part * 504;
    for (int idx = base + t; idx < base + 504; idx += 256) {
        int e = idx / LCONV, l = idx % LCONV;
        float s = cb0;
        #pragma unroll
        for (int g = 0; g < N_GRAPH; g++) {
            const float* hr = h + ((size_t)((b * N_GRAPH + g) * ELEC + e)) * HDIM + 2 * l;
            s += cw[g * 3 + 0] * fmaxf(hr[0], 0.f)
               + cw[g * 3 + 1] * fmaxf(hr[1], 0.f)
               + cw[g * 3 + 2] * fmaxf(hr[2], 0.f);
        }
        v[(size_t)b * 2016 + idx] = fmaxf(s, 0.f);
    }
}

__global__ void lin_kernel(const float* __restrict__ vg,
                           const float* __restrict__ lin1_w, const float* __restrict__ lin1_b,
                           const float* __restrict__ lin2_w, const float* __restrict__ lin2_b,
                           float* __restrict__ out) {
    int b = blockIdx.x;
    int t = threadIdx.x;
    __shared__ float v[ELEC * LCONV];
    __shared__ float u[HDIM];

    for (int i = t * 4; i < ELEC * LCONV; i += 1024) {
        float4 val = *reinterpret_cast<const float4*>(&vg[(size_t)b * 2016 + i]);
        *reinterpret_cast<float4*>(&v[i]) = val;
    }
    __syncthreads();

    int w = t >> 5, lane = t & 31;
    for (int j = w; j < HDIM; j += 8) {
        float s = 0.f;
        for (int f = lane * 4; f < ELEC * LCONV; f += 128) {
            float4 wv = *reinterpret_cast<const float4*>(&lin1_w[(size_t)j * 2016 + f]);
            float4 vv = *reinterpret_cast<const float4*>(&v[f]);
            s += wv.x * vv.x + wv.y * vv.y + wv.z * vv.z + wv.w * vv.w;
        }
        #pragma unroll
        for (int o = 16; o; o >>= 1) s += __shfl_xor_sync(0xffffffffu, s, o);
        if (lane == 0) u[j] = fmaxf(s + lin1_b[j], 0.f);
    }
    __syncthreads();

    if (t < 32) {
        float s3[3];
        #pragma unroll
        for (int j = 0; j < 3; j++) {
            float acc = 0.f;
            for (int f = t; f < HDIM; f += 32) acc += lin2_w[j * HDIM + f] * u[f];
            #pragma unroll
            for (int o = 16; o; o >>= 1) acc += __shfl_xor_sync(0xffffffffu, acc, o);
            s3[j] = acc + lin2_b[j];
        }
        if (t == 0) {
            float mx = fmaxf(s3[0], fmaxf(s3[1], s3[2]));
            float e0 = expf(s3[0] - mx), e1 = expf(s3[1] - mx), e2 = expf(s3[2] - mx);
            float inv = 1.f / (e0 + e1 + e2);
            out[b * 3 + 0] = e0 * inv;
            out[b * 3 + 1] = e1 * inv;
            out[b * 3 + 2] = e2 * inv;
        }
    }
}

// ---------------- launch ----------------
extern "C" void kernel_launch(void* const* d_in, const int* in_sizes, int n_in,
                              void* d_out, int out_size) {
    const float* x       = (const float*)d_in[0];
    const int*   ei      = (const int*)  d_in[1];
    const float* ea      = (const float*)d_in[2];
    const float* gconv_w = (const float*)d_in[4];
    const float* w_ih    = (const float*)d_in[5];
    const float* w_hh    = (const float*)d_in[6];
    const float* b_ih    = (const float*)d_in[7];
    const float* b_hh    = (const float*)d_in[8];
    const float* conv_w  = (const float*)d_in[9];
    const float* conv_b  = (const float*)d_in[10];
    const float* lin1_w  = (const float*)d_in[11];
    const float* lin1_b  = (const float*)d_in[12];
    const float* lin2_w  = (const float*)d_in[13];
    const float* lin2_b  = (const float*)d_in[14];
    float* out = (float*)d_out;

    float *ph, *pv, *pcw;
    __nv_bfloat16 *phb, *paggb, *paggc, *pqtb, *pwhb;
    int *pdeg, *pbsum, *poff, *pcur, *pcsrc;
    cudaGetSymbolAddress((void**)&ph,    g_h);
    cudaGetSymbolAddress((void**)&phb,   g_hb);
    cudaGetSymbolAddress((void**)&paggb, g_aggb);
    cudaGetSymbolAddress((void**)&paggc, g_aggc);
    cudaGetSymbolAddress((void**)&pqtb,  g_qtb);
    cudaGetSymbolAddress((void**)&pwhb,  g_whb);
    cudaGetSymbolAddress((void**)&pv,    g_v);
    cudaGetSymbolAddress((void**)&pdeg,  g_deg);
    cudaGetSymbolAddress((void**)&pbsum, g_bsum);
    cudaGetSymbolAddress((void**)&poff,  g_off);
    cudaGetSymbolAddress((void**)&pcur,  g_cur);
    cudaGetSymbolAddress((void**)&pcsrc, g_csrc);
    cudaGetSymbolAddress((void**)&pcw,   g_cw);

    cudaFuncSetAttribute(gemm_qt,    cudaFuncAttributeMaxDynamicSharedMemorySize, GEMM_SMEM);
    cudaFuncSetAttribute(gru1_fused, cudaFuncAttributeMaxDynamicSharedMemorySize, GRU1_SMEM);
    cudaFuncSetAttribute(gru_fused,  cudaFuncAttributeMaxDynamicSharedMemorySize, FUSED_SMEM);

    // Qt[l] = bf16(W_ih @ Wg_l^T)
    gemm_qt<<<dim3(3, 1, 2), 256, GEMM_SMEM>>>(w_ih, gconv_w, pqtb);

    // CSR build with parallel hierarchical scan
    zero_kernel<<<(N_NODES / 4 + 255) / 256, 256>>>((float4*)pdeg, N_NODES / 4);
    count_kernel<<<N_EDGES / 256, 256>>>(ei, pdeg);
    bsum_kernel<<<256, 256>>>(pdeg, pbsum);
    scan_tops_kernel<<<1, 256>>>(pbsum);
    off_kernel<<<256, 256>>>(pdeg, pbsum, poff, pcur);
    fill_kernel<<<N_EDGES / 256, 256>>>(ei, ea, pcur, pcsrc, pcw, w_hh, pwhb);

    // ---- layer 1: gather from x (8 lanes/node); exact K=16 GEMMs ----
    agg1c_kernel<<<N_NODES * 8 / 256, 256>>>(poff, pcsrc, pcw, x, (uint2*)paggc);
    gru1_fused<<<N_NODES / 64, 512, GRU1_SMEM>>>(paggc, ph, phb, x, pqtb, pwhb, b_ih, b_hh);

    // ---- layer 2: bf16 gather (4-edge unroll) + pipelined GEMM/GRU ----
    aggb_kernel<<<N_NODES * 16 / 256, 256>>>(poff, pcsrc, pcw,
                                             (const uint4*)phb, (uint4*)paggb);
    gru_fused<<<N_NODES / 64, 512, FUSED_SMEM>>>(paggb, ph, phb, pqtb + 49152, pwhb,
                                                 b_ih, b_hh);

    // ---- post: wide conv, then per-batch linears ----
    conv_kernel<<<dim3(BSZ, 4), 256>>>(ph, conv_w, conv_b, pv);
    lin_kernel<<<BSZ, 256>>>(pv, lin1_w, lin1_b, lin2_w, lin2_b, out);
}

// round 16
// speedup vs baseline: 1.1008x; 1.1008x over previous
#include <cuda_runtime.h>
#include <cuda_bf16.h>
#include <cuda_fp16.h>
#include <cstdint>

#define N_NODES 65536
#define N_EDGES 1048576
#define HDIM    128
#define IN_F    5
#define N_GRAPH 16
#define ELEC    32
#define BSZ     128
#define LCONV   63   // (128-3)/2+1

// ---------------- device scratch (no allocations allowed) ----------------
__device__ float           g_h   [N_NODES * HDIM];   // 32 MB fp32 h (layer-2 output only)
__device__ __nv_bfloat16   g_hb  [N_NODES * HDIM];   // 16 MB bf16 h (layer-1 output)
__device__ __nv_bfloat16   g_aggb[N_NODES * HDIM];   // 16 MB bf16 agg (layer 2)
__device__ __nv_bfloat16   g_aggc[N_NODES * 16];     // 2 MB compact agg (layer 1)
__device__ __nv_bfloat16   g_qtb [2 * 384 * HDIM];   // bf16 Qt = W_ih @ Wg^T
__device__ __nv_bfloat16   g_whb [384 * HDIM];       // bf16 w_hh
// CSR scratch
__device__ int   g_deg [N_NODES];
__device__ int   g_bsum[256];
__device__ int   g_off [N_NODES + 1];
__device__ int   g_cur [N_NODES];
__device__ int   g_csrc[N_EDGES];
__device__ float g_cw  [N_EDGES];

// ---------------- helpers ----------------
__device__ __forceinline__ unsigned int f2tf(float f) {
    unsigned int u; asm("cvt.rna.tf32.f32 %0, %1;" : "=r"(u) : "f"(f)); return u;
}

__device__ __forceinline__ void mma_tf32(float* c, const unsigned int* a, const unsigned int* b) {
    asm("mma.sync.aligned.m16n8k8.row.col.f32.tf32.tf32.f32 "
        "{%0,%1,%2,%3},{%4,%5,%6,%7},{%8,%9},{%0,%1,%2,%3};"
        : "+f"(c[0]), "+f"(c[1]), "+f"(c[2]), "+f"(c[3])
        : "r"(a[0]), "r"(a[1]), "r"(a[2]), "r"(a[3]), "r"(b[0]), "r"(b[1]));
}

__device__ __forceinline__ void mma_bf16(float* c, const unsigned int* a, const unsigned int* b) {
    asm("mma.sync.aligned.m16n8k16.row.col.f32.bf16.bf16.f32 "
        "{%0,%1,%2,%3},{%4,%5,%6,%7},{%8,%9},{%0,%1,%2,%3};"
        : "+f"(c[0]), "+f"(c[1]), "+f"(c[2]), "+f"(c[3])
        : "r"(a[0]), "r"(a[1]), "r"(a[2]), "r"(a[3]), "r"(b[0]), "r"(b[1]));
}

__device__ __forceinline__ void ldsm4(unsigned* r, unsigned addr) {
    asm volatile("ldmatrix.sync.aligned.m8n8.x4.shared.b16 {%0,%1,%2,%3}, [%4];"
        : "=r"(r[0]), "=r"(r[1]), "=r"(r[2]), "=r"(r[3]) : "r"(addr));
}

__device__ __forceinline__ void cp16(unsigned saddr, const void* gptr) {
    asm volatile("cp.async.cg.shared.global [%0], [%1], 16;" :: "r"(saddr), "l"(gptr));
}

__global__ void zero_kernel(float4* p, int n4) {
    int i = blockIdx.x * blockDim.x + threadIdx.x;
    if (i < n4) p[i] = make_float4(0.f, 0.f, 0.f, 0.f);
}

// ---------------- CSR build (parallel hierarchical scan) ----------------
__global__ void count_kernel(const int* __restrict__ ei, int* __restrict__ deg) {
    int e = blockIdx.x * blockDim.x + threadIdx.x;
    if (e < N_EDGES) atomicAdd(&deg[ei[N_EDGES + e]], 1);
}

__global__ void bsum_kernel(const int* __restrict__ deg, int* __restrict__ bsum) {
    __shared__ int s[256];
    int t = threadIdx.x;
    s[t] = deg[blockIdx.x * 256 + t];
    __syncthreads();
    #pragma unroll
    for (int o = 128; o; o >>= 1) {
        if (t < o) s[t] += s[t + o];
        __syncthreads();
    }
    if (t == 0) bsum[blockIdx.x] = s[0];
}

__global__ void scan_tops_kernel(int* __restrict__ bsum) {
    __shared__ int s[256];
    int t = threadIdx.x;
    int own = bsum[t];
    s[t] = own;
    __syncthreads();
    for (int o = 1; o < 256; o <<= 1) {
        int v = (t >= o) ? s[t - o] : 0;
        __syncthreads();
        s[t] += v;
        __syncthreads();
    }
    bsum[t] = s[t] - own;
}

__global__ void off_kernel(const int* __restrict__ deg, const int* __restrict__ bpre,
                           int* __restrict__ off, int* __restrict__ cur) {
    __shared__ int s[256];
    int t = threadIdx.x;
    int g = blockIdx.x * 256 + t;
    int own = deg[g];
    s[t] = own;
    __syncthreads();
    for (int o = 1; o < 256; o <<= 1) {
        int v = (t >= o) ? s[t - o] : 0;
        __syncthreads();
        s[t] += v;
        __syncthreads();
    }
    int val = bpre[blockIdx.x] + s[t] - own;
    off[g] = val;
    cur[g] = val;
    if (g == N_NODES - 1) off[N_NODES] = bpre[blockIdx.x] + s[t];
}

__global__ void fill_kernel(const int* __restrict__ ei, const float* __restrict__ ea,
                            int* __restrict__ cur, int* __restrict__ csrc,
                            float* __restrict__ cw,
                            const float* __restrict__ whh, __nv_bfloat16* __restrict__ whb) {
    int e = blockIdx.x * blockDim.x + threadIdx.x;
    if (e >= N_EDGES) return;
    if (e < 384 * HDIM) whb[e] = __float2bfloat16_rn(whh[e]);
    int d = ei[N_EDGES + e];
    int pos = atomicAdd(&cur[d], 1);
    csrc[pos] = ei[e];
    cw[pos]   = ea[e];
}

// ---------------- layer-2 gather: bf16 in/out, fp32 accumulate ----------------
__global__ void aggb_kernel(const int* __restrict__ off, const int* __restrict__ csrc,
                            const float* __restrict__ cw, const uint4* __restrict__ src,
                            uint4* __restrict__ dst) {
    int gid  = blockIdx.x * blockDim.x + threadIdx.x;
    int node = gid >> 4;
    int lane = gid & 15;
    if (node >= N_NODES) return;
    int e0 = __ldg(off + node), e1 = __ldg(off + node + 1);
    float acc[8] = {0.f, 0.f, 0.f, 0.f, 0.f, 0.f, 0.f, 0.f};
    int e = e0;
    for (; e + 1 < e1; e += 2) {
        int   sA = __ldg(csrc + e),     sB = __ldg(csrc + e + 1);
        float wA = __ldg(cw + e),       wB = __ldg(cw + e + 1);
        uint4 vA = __ldg(src + (size_t)sA * 16 + lane);
        uint4 vB = __ldg(src + (size_t)sB * 16 + lane);
        const unsigned* pa = &vA.x;
        const unsigned* pb = &vB.x;
        #pragma unroll
        for (int q = 0; q < 4; q++) {
            float2 fa = __bfloat1622float2(*reinterpret_cast<const __nv_bfloat162*>(&pa[q]));
            float2 fb = __bfloat1622float2(*reinterpret_cast<const __nv_bfloat162*>(&pb[q]));
            acc[2*q]   += wA * fa.x + wB * fb.x;
            acc[2*q+1] += wA * fa.y + wB * fb.y;
        }
    }
    if (e < e1) {
        int   sA = __ldg(csrc + e);
        float wA = __ldg(cw + e);
        uint4 vA = __ldg(src + (size_t)sA * 16 + lane);
        const unsigned* pa = &vA.x;
        #pragma unroll
        for (int q = 0; q < 4; q++) {
            float2 fa = __bfloat1622float2(*reinterpret_cast<const __nv_bfloat162*>(&pa[q]));
            acc[2*q]   += wA * fa.x;
            acc[2*q+1] += wA * fa.y;
        }
    }
    uint4 o;
    unsigned* po = &o.x;
    #pragma unroll
    for (int q = 0; q < 4; q++) {
        __nv_bfloat162 p = __floats2bfloat162_rn(acc[2*q], acc[2*q+1]);
        po[q] = *reinterpret_cast<unsigned*>(&p);
    }
    dst[(size_t)node * 16 + lane] = o;
}

// ---------------- layer-1 gather: directly from x -> compact bf16 agg [N][16] ----------------
__global__ void agg1c_kernel(const int* __restrict__ off, const int* __restrict__ csrc,
                             const float* __restrict__ cw, const float* __restrict__ x,
                             uint2* __restrict__ dst) {
    int gid  = blockIdx.x * blockDim.x + threadIdx.x;
    int node = gid >> 5;
    int lane = gid & 31;
    if (node >= N_NODES) return;
    int e0 = __ldg(off + node), e1 = __ldg(off + node + 1);
    float a0 = 0.f, a1 = 0.f, a2 = 0.f, a3 = 0.f, a4 = 0.f;
    for (int e = e0 + lane; e < e1; e += 32) {
        int   s = __ldg(csrc + e);
        float w = __ldg(cw + e);
        const float* xs = x + (size_t)s * IN_F;
        a0 += w * __ldg(xs);
        a1 += w * __ldg(xs + 1);
        a2 += w * __ldg(xs + 2);
        a3 += w * __ldg(xs + 3);
        a4 += w * __ldg(xs + 4);
    }
    #pragma unroll
    for (int o = 16; o; o >>= 1) {
        a0 += __shfl_xor_sync(0xffffffffu, a0, o);
        a1 += __shfl_xor_sync(0xffffffffu, a1, o);
        a2 += __shfl_xor_sync(0xffffffffu, a2, o);
        a3 += __shfl_xor_sync(0xffffffffu, a3, o);
        a4 += __shfl_xor_sync(0xffffffffu, a4, o);
    }
    if (lane < 4) {
        uint2 o = make_uint2(0u, 0u);
        if (lane == 0) {
            __nv_bfloat162 p0 = __floats2bfloat162_rn(a0, a1);
            __nv_bfloat162 p1 = __floats2bfloat162_rn(a2, a3);
            o.x = *reinterpret_cast<unsigned*>(&p0);
            o.y = *reinterpret_cast<unsigned*>(&p1);
        } else if (lane == 1) {
            __nv_bfloat162 p0 = __floats2bfloat162_rn(a4, 0.f);
            o.x = *reinterpret_cast<unsigned*>(&p0);
        }
        dst[(size_t)node * 4 + lane] = o;
    }
}

// ---------------- Qt precompute: qtb[l] = bf16(W_ih @ Wg_l^T), [384][128] ----------------
#define AS_STR 132
#define BS_STR 136
#define GEMM_SMEM ((128 * AS_STR + 128 * BS_STR) * 4)

__global__ void gemm_qt(const float* __restrict__ w_ih, const float* __restrict__ gconv_w,
                        __nv_bfloat16* __restrict__ qtb) {
    extern __shared__ unsigned int sm[];
    unsigned int* As = sm;
    unsigned int* Bs = sm + 128 * AS_STR;

    const float* A = w_ih;
    const float* Bsrc = gconv_w + (size_t)blockIdx.z * 16384;
    __nv_bfloat16* C = qtb + (size_t)blockIdx.z * 49152;

    int t  = threadIdx.x;
    int rb = blockIdx.x * 128;

    {
        const float4* A4 = reinterpret_cast<const float4*>(A) + (size_t)rb * 32;
        #pragma unroll
        for (int i = t; i < 128 * 32; i += 256) {
            int r = i >> 5, k4 = i & 31;
            float4 v = A4[r * 32 + k4];
            uint4 u = make_uint4(f2tf(v.x), f2tf(v.y), f2tf(v.z), f2tf(v.w));
            *reinterpret_cast<uint4*>(&As[r * AS_STR + k4 * 4]) = u;
        }
    }
    {
        const float4* B4 = reinterpret_cast<const float4*>(Bsrc);
        #pragma unroll
        for (int i = t; i < 128 * 32; i += 256) {
            int n = i >> 5, k4 = i & 31;
            float4 v = B4[n * 32 + k4];
            uint4 u = make_uint4(f2tf(v.x), f2tf(v.y), f2tf(v.z), f2tf(v.w));
            *reinterpret_cast<uint4*>(&Bs[n * BS_STR + k4 * 4]) = u;
        }
    }
    __syncthreads();

    int warp = t >> 5, lane = t & 31;
    int wm = (warp >> 2) * 64;
    int wn = (warp & 3) * 32;
    int lr = lane >> 2, lc = lane & 3;

    float acc[4][4][4];
    #pragma unroll
    for (int mt = 0; mt < 4; mt++)
        #pragma unroll
        for (int nt = 0; nt < 4; nt++)
            #pragma unroll
            for (int q = 0; q < 4; q++) acc[mt][nt][q] = 0.f;

    #pragma unroll
    for (int kk = 0; kk < 16; kk++) {
        int k0 = kk * 8 + lc;
        unsigned int a[4][4], b[4][2];
        #pragma unroll
        for (int mt = 0; mt < 4; mt++) {
            int r = wm + mt * 16 + lr;
            a[mt][0] = As[r * AS_STR + k0];
            a[mt][1] = As[(r + 8) * AS_STR + k0];
            a[mt][2] = As[r * AS_STR + k0 + 4];
            a[mt][3] = As[(r + 8) * AS_STR + k0 + 4];
        }
        #pragma unroll
        for (int nt = 0; nt < 4; nt++) {
            int n = wn + nt * 8 + lr;
            b[nt][0] = Bs[n * BS_STR + k0];
            b[nt][1] = Bs[n * BS_STR + k0 + 4];
        }
        #pragma unroll
        for (int mt = 0; mt < 4; mt++)
            #pragma unroll
            for (int nt = 0; nt < 4; nt++)
                mma_tf32(acc[mt][nt], a[mt], b[nt]);
    }

    #pragma unroll
    for (int nt = 0; nt < 4; nt++) {
        int c = wn + nt * 8 + lc * 2;
        #pragma unroll
        for (int mt = 0; mt < 4; mt++) {
            int r = rb + wm + mt * 16 + lr;
            __nv_bfloat162 p0 = __floats2bfloat162_rn(acc[mt][nt][0], acc[mt][nt][1]);
            __nv_bfloat162 p1 = __floats2bfloat162_rn(acc[mt][nt][2], acc[mt][nt][3]);
            *reinterpret_cast<unsigned*>(&C[(size_t)r * 128 + c]) =
                *reinterpret_cast<unsigned*>(&p0);
            *reinterpret_cast<unsigned*>(&C[(size_t)(r + 8) * 128 + c]) =
                *reinterpret_cast<unsigned*>(&p1);
        }
    }
}

// ---------------- shared GRU epilogue ----------------
// LAYER1: hold from x (cols<5), zero elsewhere; writes ONLY hb (fp32 h never read).
// LAYER2: hold from hb (bf16, same values the gh GEMM consumed); writes fp32 h.
template <int LAYER1>
__device__ __forceinline__ void gru_epilogue(
    float acc[2][3][2][4], __half2 gi_st[2][3][2][2],
    float* h, __nv_bfloat16* hb, const float* xx, const float* b_ih, const float* b_hh,
    int rb, int wr, int wc, int lr, int lc) {
    #pragma unroll
    for (int nt = 0; nt < 2; nt++) {
        int c = wc * 16 + nt * 8 + lc * 2;
        float bir0 = __ldg(b_ih + c),       bir1 = __ldg(b_ih + c + 1);
        float biz0 = __ldg(b_ih + 128 + c), biz1 = __ldg(b_ih + 128 + c + 1);
        float bin0 = __ldg(b_ih + 256 + c), bin1 = __ldg(b_ih + 256 + c + 1);
        float bhr0 = __ldg(b_hh + c),       bhr1 = __ldg(b_hh + c + 1);
        float bhz0 = __ldg(b_hh + 128 + c), bhz1 = __ldg(b_hh + 128 + c + 1);
        float bhn0 = __ldg(b_hh + 256 + c), bhn1 = __ldg(b_hh + 256 + c + 1);
        #pragma unroll
        for (int mt = 0; mt < 2; mt++) {
            #pragma unroll
            for (int half = 0; half < 2; half++) {
                int row = wr * 32 + mt * 16 + lr + half * 8;
                int q0 = half * 2;
                float2 gir = __half22float2(gi_st[mt][0][nt][half]);
                float2 giz = __half22float2(gi_st[mt][1][nt][half]);
                float2 gin = __half22float2(gi_st[mt][2][nt][half]);
                float ghr0 = acc[mt][0][nt][q0], ghr1 = acc[mt][0][nt][q0 + 1];
                float ghz0 = acc[mt][1][nt][q0], ghz1 = acc[mt][1][nt][q0 + 1];
                float ghn0 = acc[mt][2][nt][q0], ghn1 = acc[mt][2][nt][q0 + 1];
                float2 hold;
                if (LAYER1) {
                    hold = make_float2(0.f, 0.f);
                    if (c < 5) {
                        hold.x = __ldg(xx + (size_t)(rb + row) * IN_F + c);
                        if (c + 1 < 5)
                            hold.y = __ldg(xx + (size_t)(rb + row) * IN_F + c + 1);
                    }
                } else {
                    unsigned u = *reinterpret_cast<unsigned*>(&hb[(size_t)(rb + row) * 128 + c]);
                    hold = __bfloat1622float2(*reinterpret_cast<__nv_bfloat162*>(&u));
                }
                float r0 = 1.f / (1.f + __expf(-(gir.x + ghr0 + bir0 + bhr0)));
                float z0 = 1.f / (1.f + __expf(-(giz.x + ghz0 + biz0 + bhz0)));
                float n0 = tanhf(gin.x + bin0 + r0 * (ghn0 + bhn0));
                float r1 = 1.f / (1.f + __expf(-(gir.y + ghr1 + bir1 + bhr1)));
                float z1 = 1.f / (1.f + __expf(-(giz.y + ghz1 + biz1 + bhz1)));
                float n1 = tanhf(gin.y + bin1 + r1 * (ghn1 + bhn1));
                float hx = (1.f - z0) * n0 + z0 * hold.x;
                float hy = (1.f - z1) * n1 + z1 * hold.y;
                if (LAYER1) {
                    __nv_bfloat162 hp = __floats2bfloat162_rn(hx, hy);
                    *reinterpret_cast<unsigned*>(&hb[(size_t)(rb + row) * 128 + c]) =
                        *reinterpret_cast<unsigned*>(&hp);
                } else {
                    *reinterpret_cast<float2*>(&h[(size_t)(rb + row) * 128 + c]) =
                        make_float2(hx, hy);
                }
            }
        }
    }
}

// ---------------- layer-1 fused GRU: exact K=16 GEMMs; inputs from x ----------------
#define R1_STR 12
#define O_B0 (64 * R1_STR)
#define O_A1 (O_B0 + 384 * R1_STR)
#define O_B1 (O_A1 + 64 * R1_STR)
#define GRU1_SMEM ((O_B1 + 384 * R1_STR) * 4)

__global__ void __launch_bounds__(512, 1)
gru1_fused(const __nv_bfloat16* __restrict__ aggc, float* __restrict__ h,
           __nv_bfloat16* __restrict__ hb, const float* __restrict__ x,
           const __nv_bfloat16* __restrict__ w0b, const __nv_bfloat16* __restrict__ whb,
           const float* __restrict__ b_ih, const float* __restrict__ b_hh) {
    extern __shared__ char smem[];
    unsigned sb = (unsigned)__cvta_generic_to_shared(smem);

    int t = threadIdx.x;
    int rb = blockIdx.x * 64;
    int warp = t >> 5, lane = t & 31;
    int wr = warp & 1;
    int wc = warp >> 1;
    int lr = lane >> 2, lc = lane & 3;

    {
        if (t < 128) {
            int r = t >> 1, wq = (t & 1) * 4;
            cp16(sb + (unsigned)(r * R1_STR + wq) * 4, aggc + (size_t)(rb + r) * 16 + (t & 1) * 8);
        }
        #pragma unroll
        for (int i = 0; i < 3; i++) {
            int idx = t + i * 512;
            const __nv_bfloat16* W = (idx < 768) ? w0b : whb;
            int base = (idx < 768) ? O_B0 : O_B1;
            int j = (idx < 768) ? idx : idx - 768;
            int n = j >> 1, wq = (j & 1) * 4;
            cp16(sb + (unsigned)(base + n * R1_STR + wq) * 4,
                 W + (size_t)n * 128 + (j & 1) * 8);
        }
        asm volatile("cp.async.commit_group;");
        if (t >= 256 && t < 320) {
            int r = t - 256;
            const float* xs = x + (size_t)(rb + r) * IN_F;
            float x0 = __ldg(xs), x1 = __ldg(xs + 1), x2 = __ldg(xs + 2);
            float x3 = __ldg(xs + 3), x4 = __ldg(xs + 4);
            __nv_bfloat162 p0 = __floats2bfloat162_rn(x0, x1);
            __nv_bfloat162 p1 = __floats2bfloat162_rn(x2, x3);
            __nv_bfloat162 p2 = __floats2bfloat162_rn(x4, 0.f);
            unsigned* dst = reinterpret_cast<unsigned*>(smem) + O_A1 + r * R1_STR;
            dst[0] = *reinterpret_cast<unsigned*>(&p0);
            dst[1] = *reinterpret_cast<unsigned*>(&p1);
            dst[2] = *reinterpret_cast<unsigned*>(&p2);
            #pragma unroll
            for (int q = 3; q < 12; q++) dst[q] = 0u;
        }
    }
    asm volatile("cp.async.wait_group 0;");
    __syncthreads();

    int lm_m = lane >> 3, lm_r = lane & 7;
    int aRow = wr * 32 + (lm_m & 1) * 8 + lm_r;
    int aWrd = (lm_m >> 1) * 4;
    int bRow = wc * 16 + (lm_m >> 1) * 8 + lm_r;
    int bWrd = (lm_m & 1) * 4;

    float acc[2][3][2][4];
    __half2 gi_st[2][3][2][2];

    #pragma unroll
    for (int phase = 0; phase < 2; phase++) {
        unsigned abase = sb + (unsigned)((phase ? O_A1 : 0)) * 4;
        unsigned bbase = sb + (unsigned)((phase ? O_B1 : O_B0)) * 4;
        unsigned a[2][4], b[3][4];
        #pragma unroll
        for (int mt = 0; mt < 2; mt++)
            ldsm4(a[mt], abase + (unsigned)((aRow + mt * 16) * R1_STR + aWrd) * 4);
        #pragma unroll
        for (int g = 0; g < 3; g++)
            ldsm4(b[g], bbase + (unsigned)((bRow + g * 128) * R1_STR + bWrd) * 4);
        #pragma unroll
        for (int mt = 0; mt < 2; mt++)
            #pragma unroll
            for (int g = 0; g < 3; g++)
                #pragma unroll
                for (int nt = 0; nt < 2; nt++)
                    #pragma unroll
                    for (int q = 0; q < 4; q++) acc[mt][g][nt][q] = 0.f;
        #pragma unroll
        for (int mt = 0; mt < 2; mt++)
            #pragma unroll
            for (int g = 0; g < 3; g++) {
                mma_bf16(acc[mt][g][0], a[mt], &b[g][0]);
                mma_bf16(acc[mt][g][1], a[mt], &b[g][2]);
            }
        if (phase == 0) {
            #pragma unroll
            for (int mt = 0; mt < 2; mt++)
                #pragma unroll
                for (int g = 0; g < 3; g++)
                    #pragma unroll
                    for (int nt = 0; nt < 2; nt++) {
                        gi_st[mt][g][nt][0] = __floats2half2_rn(acc[mt][g][nt][0], acc[mt][g][nt][1]);
                        gi_st[mt][g][nt][1] = __floats2half2_rn(acc[mt][g][nt][2], acc[mt][g][nt][3]);
                    }
        }
    }

    gru_epilogue<1>(acc, gi_st, h, hb, x, b_ih, b_hh, rb, wr, wc, lr, lc);
}

// ---------------- layer-2 fused GRU (bf16 MMA + ldmatrix, K=64 chunks) ----------------
#define RA_STR 36
#define RB_STR 36
#define OFF_BW (2 * 64 * RA_STR)
#define FUSED_SMEM ((OFF_BW + 2 * 384 * RB_STR) * 4)

__global__ void __launch_bounds__(512, 1)
gru_fused(const __nv_bfloat16* __restrict__ aggb, float* __restrict__ h,
          __nv_bfloat16* __restrict__ hb,
          const __nv_bfloat16* __restrict__ w0b, const __nv_bfloat16* __restrict__ whb,
          const float* __restrict__ b_ih, const float* __restrict__ b_hh) {
    extern __shared__ char smem[];
    unsigned sb = (unsigned)__cvta_generic_to_shared(smem);

    int t = threadIdx.x;
    int rb = blockIdx.x * 64;
    int warp = t >> 5, lane = t & 31;
    int wr = warp & 1;
    int wc = warp >> 1;
    int lr = lane >> 2, lc = lane & 3;

    const int nch0 = 2, total = 4;

    int la_r = t >> 3, la_w = t & 7;

    auto load_chunk = [&](int j, int buf) {
        const __nv_bfloat16* A; const __nv_bfloat16* W; int kcol;
        if (j < nch0) { A = aggb; W = w0b; kcol = j * 64; }
        else          { A = hb;   W = whb; kcol = (j - nch0) * 64; }
        cp16(sb + (unsigned)(buf * (64 * RA_STR) + la_r * RA_STR + la_w * 4) * 4,
             A + (size_t)(rb + la_r) * 128 + kcol + la_w * 8);
        #pragma unroll
        for (int i = 0; i < 6; i++) {
            int idx = t + i * 512;
            int n = idx >> 3, w = idx & 7;
            cp16(sb + (unsigned)(OFF_BW + buf * (384 * RB_STR) + n * RB_STR + w * 4) * 4,
                 W + (size_t)n * 128 + kcol + w * 8);
        }
        asm volatile("cp.async.commit_group;");
    };

    load_chunk(0, 0);
    load_chunk(1, 1);

    int lm_m = lane >> 3, lm_r = lane & 7;
    int aRow = wr * 32 + (lm_m & 1) * 8 + lm_r;
    int aWrd = (lm_m >> 1) * 4;
    int bRow = wc * 16 + (lm_m >> 1) * 8 + lm_r;
    int bWrd = (lm_m & 1) * 4;

    float acc[2][3][2][4];
    __half2 gi_st[2][3][2][2];

    for (int j = 0; j < total; j++) {
        int buf = j & 1;
        if (j == 0 || j == nch0) {
            #pragma unroll
            for (int mt = 0; mt < 2; mt++)
                #pragma unroll
                for (int g = 0; g < 3; g++)
                    #pragma unroll
                    for (int nt = 0; nt < 2; nt++)
                        #pragma unroll
                        for (int q = 0; q < 4; q++) acc[mt][g][nt][q] = 0.f;
        }
        if (j + 1 < total) asm volatile("cp.async.wait_group 1;");
        else               asm volatile("cp.async.wait_group 0;");
        __syncthreads();

        unsigned abase = sb + (unsigned)(buf * (64 * RA_STR)) * 4;
        unsigned bbase = sb + (unsigned)(OFF_BW + buf * (384 * RB_STR)) * 4;
        #pragma unroll
        for (int ks = 0; ks < 4; ks++) {
            unsigned a[2][4], b[3][4];
            #pragma unroll
            for (int mt = 0; mt < 2; mt++)
                ldsm4(a[mt], abase + (unsigned)((aRow + mt * 16) * RA_STR + aWrd + ks * 8) * 4);
            #pragma unroll
            for (int g = 0; g < 3; g++)
                ldsm4(b[g], bbase + (unsigned)((bRow + g * 128) * RB_STR + bWrd + ks * 8) * 4);
            #pragma unroll
            for (int mt = 0; mt < 2; mt++)
                #pragma unroll
                for (int g = 0; g < 3; g++) {
                    mma_bf16(acc[mt][g][0], a[mt], &b[g][0]);
                    mma_bf16(acc[mt][g][1], a[mt], &b[g][2]);
                }
        }
        __syncthreads();
        if (j + 2 < total) load_chunk(j + 2, buf);

        if (j == nch0 - 1) {
            #pragma unroll
            for (int mt = 0; mt < 2; mt++)
                #pragma unroll
                for (int g = 0; g < 3; g++)
                    #pragma unroll
                    for (int nt = 0; nt < 2; nt++) {
                        gi_st[mt][g][nt][0] = __floats2half2_rn(acc[mt][g][nt][0], acc[mt][g][nt][1]);
                        gi_st[mt][g][nt][1] = __floats2half2_rn(acc[mt][g][nt][2], acc[mt][g][nt][3]);
                    }
        }
    }

    gru_epilogue<0>(acc, gi_st, h, hb, nullptr, b_ih, b_hh, rb, wr, wc, lr, lc);
}

// ---------------- post ----------------
__global__ void post_kernel(const float* __restrict__ h,
                            const float* __restrict__ conv_w, const float* __restrict__ conv_b,
                            const float* __restrict__ lin1_w, const float* __restrict__ lin1_b,
                            const float* __restrict__ lin2_w, const float* __restrict__ lin2_b,
                            float* __restrict__ out) {
    int b = blockIdx.x;
    int t = threadIdx.x;
    __shared__ float cw[48];
    __shared__ float v[ELEC * LCONV];
    __shared__ float u[HDIM];

    if (t < 48) cw[t] = conv_w[t];
    __syncthreads();
    float cb0 = conv_b[0];

    for (int idx = t; idx < ELEC * LCONV; idx += 256) {
        int e = idx / LCONV, l = idx % LCONV;
        float s = cb0;
        #pragma unroll
        for (int g = 0; g < N_GRAPH; g++) {
            const float* hr = h + ((size_t)((b * N_GRAPH + g) * ELEC + e)) * HDIM + 2 * l;
            s += cw[g * 3 + 0] * fmaxf(hr[0], 0.f)
               + cw[g * 3 + 1] * fmaxf(hr[1], 0.f)
               + cw[g * 3 + 2] * fmaxf(hr[2], 0.f);
        }
        v[idx] = fmaxf(s, 0.f);
    }
    __syncthreads();

    int w = t >> 5, lane = t & 31;
    for (int j = w; j < HDIM; j += 8) {
        float s = 0.f;
        for (int f = lane * 4; f < ELEC * LCONV; f += 128) {
            float4 wv = *reinterpret_cast<const float4*>(&lin1_w[(size_t)j * 2016 + f]);
            float4 vv = *reinterpret_cast<const float4*>(&v[f]);
            s += wv.x * vv.x + wv.y * vv.y + wv.z * vv.z + wv.w * vv.w;
        }
        #pragma unroll
        for (int o = 16; o; o >>= 1) s += __shfl_xor_sync(0xffffffffu, s, o);
        if (lane == 0) u[j] = fmaxf(s + lin1_b[j], 0.f);
    }
    __syncthreads();

    if (t < 32) {
        float s3[3];
        #pragma unroll
        for (int j = 0; j < 3; j++) {
            float acc = 0.f;
            for (int f = t; f < HDIM; f += 32) acc += lin2_w[j * HDIM + f] * u[f];
            #pragma unroll
            for (int o = 16; o; o >>= 1) acc += __shfl_xor_sync(0xffffffffu, acc, o);
            s3[j] = acc + lin2_b[j];
        }
        if (t == 0) {
            float mx = fmaxf(s3[0], fmaxf(s3[1], s3[2]));
            float e0 = expf(s3[0] - mx), e1 = expf(s3[1] - mx), e2 = expf(s3[2] - mx);
            float inv = 1.f / (e0 + e1 + e2);
            out[b * 3 + 0] = e0 * inv;
            out[b * 3 + 1] = e1 * inv;
            out[b * 3 + 2] = e2 * inv;
        }
    }
}

// ---------------- launch ----------------
extern "C" void kernel_launch(void* const* d_in, const int* in_sizes, int n_in,
                              void* d_out, int out_size) {
    const float* x       = (const float*)d_in[0];
    const int*   ei      = (const int*)  d_in[1];
    const float* ea      = (const float*)d_in[2];
    const float* gconv_w = (const float*)d_in[4];
    const float* w_ih    = (const float*)d_in[5];
    const float* w_hh    = (const float*)d_in[6];
    const float* b_ih    = (const float*)d_in[7];
    const float* b_hh    = (const float*)d_in[8];
    const float* conv_w  = (const float*)d_in[9];
    const float* conv_b  = (const float*)d_in[10];
    const float* lin1_w  = (const float*)d_in[11];
    const float* lin1_b  = (const float*)d_in[12];
    const float* lin2_w  = (const float*)d_in[13];
    const float* lin2_b  = (const float*)d_in[14];
    float* out = (float*)d_out;

    float *ph, *pcw;
    __nv_bfloat16 *phb, *paggb, *paggc, *pqtb, *pwhb;
    int *pdeg, *pbsum, *poff, *pcur, *pcsrc;
    cudaGetSymbolAddress((void**)&ph,    g_h);
    cudaGetSymbolAddress((void**)&phb,   g_hb);
    cudaGetSymbolAddress((void**)&paggb, g_aggb);
    cudaGetSymbolAddress((void**)&paggc, g_aggc);
    cudaGetSymbolAddress((void**)&pqtb,  g_qtb);
    cudaGetSymbolAddress((void**)&pwhb,  g_whb);
    cudaGetSymbolAddress((void**)&pdeg,  g_deg);
    cudaGetSymbolAddress((void**)&pbsum, g_bsum);
    cudaGetSymbolAddress((void**)&poff,  g_off);
    cudaGetSymbolAddress((void**)&pcur,  g_cur);
    cudaGetSymbolAddress((void**)&pcsrc, g_csrc);
    cudaGetSymbolAddress((void**)&pcw,   g_cw);

    cudaFuncSetAttribute(gemm_qt,    cudaFuncAttributeMaxDynamicSharedMemorySize, GEMM_SMEM);
    cudaFuncSetAttribute(gru1_fused, cudaFuncAttributeMaxDynamicSharedMemorySize, GRU1_SMEM);
    cudaFuncSetAttribute(gru_fused,  cudaFuncAttributeMaxDynamicSharedMemorySize, FUSED_SMEM);

    // Qt[l] = bf16(W_ih @ Wg_l^T)
    gemm_qt<<<dim3(3, 1, 2), 256, GEMM_SMEM>>>(w_ih, gconv_w, pqtb);

    // CSR build with parallel hierarchical scan
    zero_kernel<<<(N_NODES / 4 + 255) / 256, 256>>>((float4*)pdeg, N_NODES / 4);
    count_kernel<<<N_EDGES / 256, 256>>>(ei, pdeg);
    bsum_kernel<<<256, 256>>>(pdeg, pbsum);
    scan_tops_kernel<<<1, 256>>>(pbsum);
    off_kernel<<<256, 256>>>(pdeg, pbsum, poff, pcur);
    fill_kernel<<<N_EDGES / 256, 256>>>(ei, ea, pcur, pcsrc, pcw, w_hh, pwhb);

    // ---- layer 1: gather from x; exact K=16 GEMMs; writes hb only ----
    agg1c_kernel<<<N_NODES * 32 / 256, 256>>>(poff, pcsrc, pcw, x, (uint2*)paggc);
    gru1_fused<<<N_NODES / 64, 512, GRU1_SMEM>>>(paggc, ph, phb, x, pqtb, pwhb, b_ih, b_hh);

    // ---- layer 2: bf16 gather + pipelined GEMM/GRU; hold from hb; writes fp32 h ----
    aggb_kernel<<<N_NODES * 16 / 256, 256>>>(poff, pcsrc, pcw,
                                             (const uint4*)phb, (uint4*)paggb);
    gru_fused<<<N_NODES / 64, 512, FUSED_SMEM>>>(paggb, ph, phb, pqtb + 49152, pwhb,
                                                 b_ih, b_hh);

    post_kernel<<<BSZ, 256>>>(ph, conv_w, conv_b, lin1_w, lin1_b, lin2_w, lin2_b, out);
}